// round 5
// baseline (speedup 1.0000x reference)
#include <cuda_runtime.h>

#define BATCH 4
#define SEQ   2048
#define NHEAD 16
#define HDIM  64
#define HID   1024
#define NEG_F (-3.4028234663852886e38f)

// Scratch: Q/K/V in [b*NH + h][s][d] layout (fp32). ~33.5MB each, device globals
// (allocation-guard-safe).
__device__ float g_q[BATCH * NHEAD * SEQ * HDIM];
__device__ float g_k[BATCH * NHEAD * SEQ * HDIM];
__device__ float g_v[BATCH * NHEAD * SEQ * HDIM];

__device__ __forceinline__ float neg_inf_f() { return __int_as_float(0xff800000); }

// ---------------------------------------------------------------------------
// Kernel 1: Y = X @ W + b for W in {Wq,Wk,Wv} (blockIdx.z selects).
// M=8192, N=1024, K=1024. Tiles: BM=128, BN=128, BK=16. 256 threads, 8x8 micro.
// Output written directly into [bh][s][d] scratch layout.
// ---------------------------------------------------------------------------
__global__ __launch_bounds__(256) void qkv_kernel(
    const float* __restrict__ X,
    const float* __restrict__ Wq, const float* __restrict__ Bq,
    const float* __restrict__ Wk, const float* __restrict__ Bk,
    const float* __restrict__ Wv, const float* __restrict__ Bv)
{
    const int z = blockIdx.z;
    const float* __restrict__ W  = (z == 0) ? Wq : (z == 1) ? Wk : Wv;
    const float* __restrict__ Bi = (z == 0) ? Bq : (z == 1) ? Bk : Bv;
    float* __restrict__ dst      = (z == 0) ? g_q : (z == 1) ? g_k : g_v;

    __shared__ float XsT[16][132];   // [k][m], padded row (132) vs bank conflicts
    __shared__ float Ws[16][128];    // [k][n]

    const int tid = threadIdx.x;
    const int tx  = tid & 15;        // n dim: 16 x 8 = 128
    const int ty  = tid >> 4;        // m dim: 16 x 8 = 128
    const int m0  = blockIdx.y * 128;
    const int n0  = blockIdx.x * 128;

    float acc[8][8];
#pragma unroll
    for (int i = 0; i < 8; i++)
#pragma unroll
        for (int j = 0; j < 8; j++) acc[i][j] = 0.f;

    for (int k0 = 0; k0 < HID; k0 += 16) {
        // Load X tile (128x16), store transposed. 512 float4s, 2 per thread.
#pragma unroll
        for (int p = 0; p < 2; p++) {
            int i  = tid + p * 256;      // 0..511
            int ml = i >> 2;             // 0..127
            int kq = i & 3;              // which float4 in k
            float4 v = *(const float4*)(X + (size_t)(m0 + ml) * HID + k0 + kq * 4);
            XsT[kq * 4 + 0][ml] = v.x;
            XsT[kq * 4 + 1][ml] = v.y;
            XsT[kq * 4 + 2][ml] = v.z;
            XsT[kq * 4 + 3][ml] = v.w;
        }
        // Load W tile (16x128). 512 float4s, 2 per thread, coalesced.
#pragma unroll
        for (int p = 0; p < 2; p++) {
            int i  = tid + p * 256;      // 0..511
            int kr = i >> 5;             // 0..15
            int nq = i & 31;             // 0..31
            float4 v = *(const float4*)(W + (size_t)(k0 + kr) * HID + n0 + nq * 4);
            *(float4*)&Ws[kr][nq * 4] = v;
        }
        __syncthreads();
#pragma unroll
        for (int kk = 0; kk < 16; kk++) {
            float4 a0 = *(const float4*)&XsT[kk][ty * 8];
            float4 a1 = *(const float4*)&XsT[kk][ty * 8 + 4];
            float4 b0 = *(const float4*)&Ws[kk][tx * 8];
            float4 b1 = *(const float4*)&Ws[kk][tx * 8 + 4];
            float a[8] = {a0.x, a0.y, a0.z, a0.w, a1.x, a1.y, a1.z, a1.w};
            float bb[8] = {b0.x, b0.y, b0.z, b0.w, b1.x, b1.y, b1.z, b1.w};
#pragma unroll
            for (int i = 0; i < 8; i++)
#pragma unroll
                for (int j = 0; j < 8; j++)
                    acc[i][j] = fmaf(a[i], bb[j], acc[i][j]);
        }
        __syncthreads();
    }

    // My 8 output columns all fall inside one head: (tx*8) % 64 ∈ {0,...,56}.
    const int ncol = n0 + tx * 8;
    const int h    = ncol >> 6;          // head index
    const int d0   = ncol & 63;          // offset within head
    float4 bA = *(const float4*)(Bi + ncol);
    float4 bB = *(const float4*)(Bi + ncol + 4);
    const float bb[8] = {bA.x, bA.y, bA.z, bA.w, bB.x, bB.y, bB.z, bB.w};
#pragma unroll
    for (int i = 0; i < 8; i++) {
        int m = m0 + ty * 8 + i;
        int bi = m >> 11;            // m / SEQ
        int s  = m & (SEQ - 1);
        float* p = dst + ((size_t)(bi * NHEAD + h) * SEQ + s) * HDIM + d0;
        float4 o0, o1;
        o0.x = acc[i][0] + bb[0]; o0.y = acc[i][1] + bb[1];
        o0.z = acc[i][2] + bb[2]; o0.w = acc[i][3] + bb[3];
        o1.x = acc[i][4] + bb[4]; o1.y = acc[i][5] + bb[5];
        o1.z = acc[i][6] + bb[6]; o1.w = acc[i][7] + bb[7];
        *(float4*)(p)     = o0;
        *(float4*)(p + 4) = o1;
    }
}

// ---------------------------------------------------------------------------
// Kernel 2: flash attention, one (bh, 64-query tile) per block. 256 threads.
// Q/K staged d-major ([d][q]) so the S=QK^T inner loop uses intra-row float4
// LDS (conflict-free). P aliased into the K buffer. 48KB static smem exactly.
// Mask read as int32 (JAX x64-disabled narrows the declared int64 to int32).
// ---------------------------------------------------------------------------
__global__ __launch_bounds__(256) void attn_kernel(
    const int* __restrict__ mask,
    float* __restrict__ out)
{
    __shared__ float QsT[64 * 64];   // [d][q]
    __shared__ float KsP[64 * 64];   // phase 1: K^T [d][k]; phase 2: P [q][k]
    __shared__ float Vs [64 * 64];   // [k][d]

    const int tid = threadIdx.x;
    const int tx  = tid & 15;        // key-col / out-col dim
    const int ty  = tid >> 4;        // query-row dim
    const int r0  = ty * 4;
    const int c0  = tx * 4;
    const int q0  = blockIdx.x * 64;
    const int bh  = blockIdx.y;
    const int b   = bh >> 4;
    const int h   = bh & 15;

    const float* __restrict__ Q = g_q + (size_t)bh * SEQ * HDIM;
    const float* __restrict__ K = g_k + (size_t)bh * SEQ * HDIM;
    const float* __restrict__ V = g_v + (size_t)bh * SEQ * HDIM;
    const int* __restrict__ mrow = mask + (size_t)b * SEQ;

    // Load Q transposed.
#pragma unroll
    for (int p = 0; p < 4; p++) {
        int idx = tid + p * 256;        // 0..1023 float4s
        int ql  = idx & 63;
        int dq  = idx >> 6;             // 0..15
        float4 v = *(const float4*)(Q + (size_t)(q0 + ql) * HDIM + dq * 4);
        QsT[(dq * 4 + 0) * 64 + ql] = v.x;
        QsT[(dq * 4 + 1) * 64 + ql] = v.y;
        QsT[(dq * 4 + 2) * 64 + ql] = v.z;
        QsT[(dq * 4 + 3) * 64 + ql] = v.w;
    }

    float acc[4][4];
    float mprev[4], lsum[4];
#pragma unroll
    for (int i = 0; i < 4; i++) {
        mprev[i] = neg_inf_f();
        lsum[i]  = 0.f;
#pragma unroll
        for (int j = 0; j < 4; j++) acc[i][j] = 0.f;
    }

    for (int kt = 0; kt < SEQ / 64; kt++) {
        const int k0 = kt * 64;
        __syncthreads();   // prev-iter P/V reads done; (iter 0) Q visible

        // Load K transposed + V natural.
#pragma unroll
        for (int p = 0; p < 4; p++) {
            int idx = tid + p * 256;
            int kl = idx & 63, dq = idx >> 6;
            float4 v = *(const float4*)(K + (size_t)(k0 + kl) * HDIM + dq * 4);
            KsP[(dq * 4 + 0) * 64 + kl] = v.x;
            KsP[(dq * 4 + 1) * 64 + kl] = v.y;
            KsP[(dq * 4 + 2) * 64 + kl] = v.z;
            KsP[(dq * 4 + 3) * 64 + kl] = v.w;
            int vl = idx >> 4, dv = idx & 15;
            float4 w = *(const float4*)(V + (size_t)(k0 + vl) * HDIM + dv * 4);
            *(float4*)&Vs[vl * 64 + dv * 4] = w;
        }
        __syncthreads();

        // S = Q K^T  (64x64 tile, 4x4 per thread)
        float s[4][4];
#pragma unroll
        for (int i = 0; i < 4; i++)
#pragma unroll
            for (int j = 0; j < 4; j++) s[i][j] = 0.f;

#pragma unroll 8
        for (int d = 0; d < HDIM; d++) {
            float4 a4 = *(const float4*)&QsT[d * 64 + r0];
            float4 k4 = *(const float4*)&KsP[d * 64 + c0];
            float aa[4] = {a4.x, a4.y, a4.z, a4.w};
            float kk[4] = {k4.x, k4.y, k4.z, k4.w};
#pragma unroll
            for (int i = 0; i < 4; i++)
#pragma unroll
                for (int j = 0; j < 4; j++)
                    s[i][j] = fmaf(aa[i], kk[j], s[i][j]);
        }

        // Mask bias for my 4 key columns (select form: 0 if kept, NEG if masked;
        // identical to (1-m)*finfo.min for 0/1 masks, and inf-proof).
        float biasr[4];
#pragma unroll
        for (int j = 0; j < 4; j++)
            biasr[j] = (mrow[k0 + c0 + j] != 0) ? 0.f : NEG_F;

        // Online softmax update. Row groups = 16 tx-lanes, xor-shfl {8,4,2,1}.
        float p4[4][4];
#pragma unroll
        for (int i = 0; i < 4; i++) {
            float mx = neg_inf_f();
#pragma unroll
            for (int j = 0; j < 4; j++) {
                s[i][j] = fmaf(s[i][j], 0.125f, biasr[j]);   // 1/sqrt(64)
                mx = fmaxf(mx, s[i][j]);
            }
            mx = fmaxf(mx, __shfl_xor_sync(0xffffffffu, mx, 8));
            mx = fmaxf(mx, __shfl_xor_sync(0xffffffffu, mx, 4));
            mx = fmaxf(mx, __shfl_xor_sync(0xffffffffu, mx, 2));
            mx = fmaxf(mx, __shfl_xor_sync(0xffffffffu, mx, 1));
            float mnew = fmaxf(mprev[i], mx);
            float sf   = __expf(mprev[i] - mnew);
            float rs   = 0.f;
#pragma unroll
            for (int j = 0; j < 4; j++) {
                p4[i][j] = __expf(s[i][j] - mnew);
                rs += p4[i][j];
            }
            rs += __shfl_xor_sync(0xffffffffu, rs, 8);
            rs += __shfl_xor_sync(0xffffffffu, rs, 4);
            rs += __shfl_xor_sync(0xffffffffu, rs, 2);
            rs += __shfl_xor_sync(0xffffffffu, rs, 1);
            lsum[i]  = lsum[i] * sf + rs;
            mprev[i] = mnew;
#pragma unroll
            for (int j = 0; j < 4; j++) acc[i][j] *= sf;
        }
        __syncthreads();   // everyone done reading KsP as K^T

        // Store P (natural [q][k] layout) into the K buffer.
#pragma unroll
        for (int i = 0; i < 4; i++) {
            float4 pv = make_float4(p4[i][0], p4[i][1], p4[i][2], p4[i][3]);
            *(float4*)&KsP[(r0 + i) * 64 + c0] = pv;
        }
        __syncthreads();

        // O += P V  (inner dim = 64 keys, 4 at a time)
#pragma unroll 4
        for (int j4 = 0; j4 < 16; j4++) {
            float4 v0 = *(const float4*)&Vs[(j4 * 4 + 0) * 64 + c0];
            float4 v1 = *(const float4*)&Vs[(j4 * 4 + 1) * 64 + c0];
            float4 v2 = *(const float4*)&Vs[(j4 * 4 + 2) * 64 + c0];
            float4 v3 = *(const float4*)&Vs[(j4 * 4 + 3) * 64 + c0];
            float bv[4][4] = {{v0.x, v0.y, v0.z, v0.w},
                              {v1.x, v1.y, v1.z, v1.w},
                              {v2.x, v2.y, v2.z, v2.w},
                              {v3.x, v3.y, v3.z, v3.w}};
#pragma unroll
            for (int i = 0; i < 4; i++) {
                float4 a4 = *(const float4*)&KsP[(r0 + i) * 64 + j4 * 4];
                float aa[4] = {a4.x, a4.y, a4.z, a4.w};
#pragma unroll
                for (int c = 0; c < 4; c++)
#pragma unroll
                    for (int jj = 0; jj < 4; jj++)
                        acc[i][c] = fmaf(aa[jj], bv[jj][c], acc[i][c]);
            }
        }
    }

    // Epilogue: out[b][s][h*64 + d] = acc / l
#pragma unroll
    for (int i = 0; i < 4; i++) {
        float inv = 1.0f / lsum[i];
        float4 o = make_float4(acc[i][0] * inv, acc[i][1] * inv,
                               acc[i][2] * inv, acc[i][3] * inv);
        int srow = q0 + r0 + i;
        *(float4*)(out + ((size_t)(b * SEQ + srow)) * HID + h * HDIM + c0) = o;
    }
}

extern "C" void kernel_launch(void* const* d_in, const int* in_sizes, int n_in,
                              void* d_out, int out_size) {
    const float* X    = (const float*)d_in[0];
    const int*   mask = (const int*)d_in[1];
    const float* Wq   = (const float*)d_in[2];
    const float* Bq   = (const float*)d_in[3];
    const float* Wk   = (const float*)d_in[4];
    const float* Bk   = (const float*)d_in[5];
    const float* Wv   = (const float*)d_in[6];
    const float* Bv   = (const float*)d_in[7];
    float* out = (float*)d_out;

    dim3 g1(HID / 128, (BATCH * SEQ) / 128, 3);
    qkv_kernel<<<g1, 256>>>(X, Wq, Bq, Wk, Bk, Wv, Bv);

    dim3 g2(SEQ / 64, BATCH * NHEAD);
    attn_kernel<<<g2, 256>>>(mask, out);
}

// round 6
// speedup vs baseline: 1.0990x; 1.0990x over previous
#include <cuda_runtime.h>

#define BATCH 4
#define SEQ   2048
#define NHEAD 16
#define HDIM  64
#define HID   1024
#define NEG_F (-3.4028234663852886e38f)

// Scratch: Q/K/V in [b*NH + h][s][d] layout (fp32), device globals.
__device__ float g_q[BATCH * NHEAD * SEQ * HDIM];
__device__ float g_k[BATCH * NHEAD * SEQ * HDIM];
__device__ float g_v[BATCH * NHEAD * SEQ * HDIM];

__device__ __forceinline__ float neg_inf_f() { return __int_as_float(0xff800000); }

// ---------------------------------------------------------------------------
// Kernel 1: Y = X @ W + b for W in {Wq,Wk,Wv} (blockIdx.z selects).
// BM=128, BN=128, BK=16, 256 threads, 8x8 micro. (unchanged — ~73% of fp32 roof)
// ---------------------------------------------------------------------------
__global__ __launch_bounds__(256) void qkv_kernel(
    const float* __restrict__ X,
    const float* __restrict__ Wq, const float* __restrict__ Bq,
    const float* __restrict__ Wk, const float* __restrict__ Bk,
    const float* __restrict__ Wv, const float* __restrict__ Bv)
{
    const int z = blockIdx.z;
    const float* __restrict__ W  = (z == 0) ? Wq : (z == 1) ? Wk : Wv;
    const float* __restrict__ Bi = (z == 0) ? Bq : (z == 1) ? Bk : Bv;
    float* __restrict__ dst      = (z == 0) ? g_q : (z == 1) ? g_k : g_v;

    __shared__ float XsT[16][132];
    __shared__ float Ws[16][128];

    const int tid = threadIdx.x;
    const int tx  = tid & 15;
    const int ty  = tid >> 4;
    const int m0  = blockIdx.y * 128;
    const int n0  = blockIdx.x * 128;

    float acc[8][8];
#pragma unroll
    for (int i = 0; i < 8; i++)
#pragma unroll
        for (int j = 0; j < 8; j++) acc[i][j] = 0.f;

    for (int k0 = 0; k0 < HID; k0 += 16) {
#pragma unroll
        for (int p = 0; p < 2; p++) {
            int i  = tid + p * 256;
            int ml = i >> 2;
            int kq = i & 3;
            float4 v = *(const float4*)(X + (size_t)(m0 + ml) * HID + k0 + kq * 4);
            XsT[kq * 4 + 0][ml] = v.x;
            XsT[kq * 4 + 1][ml] = v.y;
            XsT[kq * 4 + 2][ml] = v.z;
            XsT[kq * 4 + 3][ml] = v.w;
        }
#pragma unroll
        for (int p = 0; p < 2; p++) {
            int i  = tid + p * 256;
            int kr = i >> 5;
            int nq = i & 31;
            float4 v = *(const float4*)(W + (size_t)(k0 + kr) * HID + n0 + nq * 4);
            *(float4*)&Ws[kr][nq * 4] = v;
        }
        __syncthreads();
#pragma unroll
        for (int kk = 0; kk < 16; kk++) {
            float4 a0 = *(const float4*)&XsT[kk][ty * 8];
            float4 a1 = *(const float4*)&XsT[kk][ty * 8 + 4];
            float4 b0 = *(const float4*)&Ws[kk][tx * 8];
            float4 b1 = *(const float4*)&Ws[kk][tx * 8 + 4];
            float a[8] = {a0.x, a0.y, a0.z, a0.w, a1.x, a1.y, a1.z, a1.w};
            float bb[8] = {b0.x, b0.y, b0.z, b0.w, b1.x, b1.y, b1.z, b1.w};
#pragma unroll
            for (int i = 0; i < 8; i++)
#pragma unroll
                for (int j = 0; j < 8; j++)
                    acc[i][j] = fmaf(a[i], bb[j], acc[i][j]);
        }
        __syncthreads();
    }

    const int ncol = n0 + tx * 8;
    const int h    = ncol >> 6;
    const int d0   = ncol & 63;
    float4 bA = *(const float4*)(Bi + ncol);
    float4 bB = *(const float4*)(Bi + ncol + 4);
    const float bb[8] = {bA.x, bA.y, bA.z, bA.w, bB.x, bB.y, bB.z, bB.w};
#pragma unroll
    for (int i = 0; i < 8; i++) {
        int m = m0 + ty * 8 + i;
        int bi = m >> 11;
        int s  = m & (SEQ - 1);
        float* p = dst + ((size_t)(bi * NHEAD + h) * SEQ + s) * HDIM + d0;
        float4 o0, o1;
        o0.x = acc[i][0] + bb[0]; o0.y = acc[i][1] + bb[1];
        o0.z = acc[i][2] + bb[2]; o0.w = acc[i][3] + bb[3];
        o1.x = acc[i][4] + bb[4]; o1.y = acc[i][5] + bb[5];
        o1.z = acc[i][6] + bb[6]; o1.w = acc[i][7] + bb[7];
        *(float4*)(p)     = o0;
        *(float4*)(p + 4) = o1;
    }
}

// ---------------------------------------------------------------------------
// Kernel 2: flash attention, BQ=128 x BK=128 tiles, 256 threads.
// S micro = 8q x 8k (cols tx*4 and 64+tx*4 — contiguous float4 groups,
// conflict-free). PV micro = 8q x 4d. Smem (dynamic, 128KB):
//   QsT [64][128]  (d-major Q)                     offset 0      (32KB)
//   UN  [16384]    KT [64][128] then P [128][128]  offset 8192   (64KB)
//   Vs  [128][64]                                  offset 24576  (32KB)
// 1 CTA/SM; P overwrites KT after the S phase (sync-ordered).
// ---------------------------------------------------------------------------
__global__ __launch_bounds__(256) void attn_kernel(
    const int* __restrict__ mask,
    float* __restrict__ out)
{
    extern __shared__ float sm[];
    float* QsT = sm;            // [d][q]  64x128
    float* UN  = sm + 8192;     // KT [d][k] 64x128, then P [q][k] 128x128
    float* Vs  = sm + 24576;    // [k][d] 128x64

    const int tid = threadIdx.x;
    const int tx  = tid & 15;
    const int ty  = tid >> 4;
    const int r0  = ty * 8;          // 8 query rows
    const int cA  = tx * 4;          // S k-cols group A
    const int cB  = 64 + tx * 4;     // S k-cols group B
    const int q0  = blockIdx.x * 128;
    const int bh  = blockIdx.y;
    const int b   = bh >> 4;
    const int h   = bh & 15;

    const float* __restrict__ Q = g_q + (size_t)bh * SEQ * HDIM;
    const float* __restrict__ K = g_k + (size_t)bh * SEQ * HDIM;
    const float* __restrict__ V = g_v + (size_t)bh * SEQ * HDIM;
    const int* __restrict__ mrow = mask + (size_t)b * SEQ;

    // Load Q (128 rows x 64 d) transposed into QsT. 2048 float4s, 8/thread.
#pragma unroll
    for (int p = 0; p < 8; p++) {
        int idx = tid + p * 256;
        int ql  = idx & 127;
        int dq  = idx >> 7;          // 0..15
        float4 v = *(const float4*)(Q + (size_t)(q0 + ql) * HDIM + dq * 4);
        QsT[(dq * 4 + 0) * 128 + ql] = v.x;
        QsT[(dq * 4 + 1) * 128 + ql] = v.y;
        QsT[(dq * 4 + 2) * 128 + ql] = v.z;
        QsT[(dq * 4 + 3) * 128 + ql] = v.w;
    }

    float acc[8][4];
    float mprev[8], lsum[8];
#pragma unroll
    for (int i = 0; i < 8; i++) {
        mprev[i] = neg_inf_f();
        lsum[i]  = 0.f;
#pragma unroll
        for (int j = 0; j < 4; j++) acc[i][j] = 0.f;
    }

    for (int kt = 0; kt < SEQ / 128; kt++) {
        const int k0 = kt * 128;
        __syncthreads();   // prev-iter P/V reads done; (iter 0) Q visible

        // K (128 x 64) transposed into KT(=UN), V (128 x 64) natural into Vs.
#pragma unroll
        for (int p = 0; p < 8; p++) {
            int idx = tid + p * 256;
            int kl = idx & 127, dq = idx >> 7;
            float4 v = *(const float4*)(K + (size_t)(k0 + kl) * HDIM + dq * 4);
            UN[(dq * 4 + 0) * 128 + kl] = v.x;
            UN[(dq * 4 + 1) * 128 + kl] = v.y;
            UN[(dq * 4 + 2) * 128 + kl] = v.z;
            UN[(dq * 4 + 3) * 128 + kl] = v.w;
            int vl = idx >> 4, dv = idx & 15;
            float4 w = *(const float4*)(V + (size_t)(k0 + vl) * HDIM + dv * 4);
            *(float4*)&Vs[vl * 64 + dv * 4] = w;
        }
        __syncthreads();

        // S = Q K^T : 8x8 per thread. Q reads broadcast across tx; K reads
        // contiguous float4 groups (conflict-free).
        float s[8][8];
#pragma unroll
        for (int i = 0; i < 8; i++)
#pragma unroll
            for (int j = 0; j < 8; j++) s[i][j] = 0.f;

#pragma unroll 4
        for (int d = 0; d < HDIM; d++) {
            float4 a0 = *(const float4*)&QsT[d * 128 + r0];
            float4 a1 = *(const float4*)&QsT[d * 128 + r0 + 4];
            float4 b0 = *(const float4*)&UN[d * 128 + cA];
            float4 b1 = *(const float4*)&UN[d * 128 + cB];
            float a[8] = {a0.x, a0.y, a0.z, a0.w, a1.x, a1.y, a1.z, a1.w};
            float bb[8] = {b0.x, b0.y, b0.z, b0.w, b1.x, b1.y, b1.z, b1.w};
#pragma unroll
            for (int i = 0; i < 8; i++)
#pragma unroll
                for (int j = 0; j < 8; j++)
                    s[i][j] = fmaf(a[i], bb[j], s[i][j]);
        }

        // Mask bias (select form; inf-proof for 0/1 masks).
        float bias[8];
#pragma unroll
        for (int j = 0; j < 4; j++) {
            bias[j]     = (mrow[k0 + cA + j] != 0) ? 0.f : NEG_F;
            bias[4 + j] = (mrow[k0 + cB + j] != 0) ? 0.f : NEG_F;
        }

        // Online softmax; rows reduce across the 16 tx lanes (xor 8,4,2,1).
#pragma unroll
        for (int i = 0; i < 8; i++) {
            float mx = neg_inf_f();
#pragma unroll
            for (int j = 0; j < 8; j++) {
                s[i][j] = fmaf(s[i][j], 0.125f, bias[j]);   // 1/sqrt(64)
                mx = fmaxf(mx, s[i][j]);
            }
            mx = fmaxf(mx, __shfl_xor_sync(0xffffffffu, mx, 8));
            mx = fmaxf(mx, __shfl_xor_sync(0xffffffffu, mx, 4));
            mx = fmaxf(mx, __shfl_xor_sync(0xffffffffu, mx, 2));
            mx = fmaxf(mx, __shfl_xor_sync(0xffffffffu, mx, 1));
            float mnew = fmaxf(mprev[i], mx);
            float sf   = __expf(mprev[i] - mnew);
            float rs   = 0.f;
#pragma unroll
            for (int j = 0; j < 8; j++) {
                s[i][j] = __expf(s[i][j] - mnew);   // s -> p in place
                rs += s[i][j];
            }
            rs += __shfl_xor_sync(0xffffffffu, rs, 8);
            rs += __shfl_xor_sync(0xffffffffu, rs, 4);
            rs += __shfl_xor_sync(0xffffffffu, rs, 2);
            rs += __shfl_xor_sync(0xffffffffu, rs, 1);
            lsum[i]  = lsum[i] * sf + rs;
            mprev[i] = mnew;
#pragma unroll
            for (int j = 0; j < 4; j++) acc[i][j] *= sf;
        }
        __syncthreads();   // all KT reads done before P overwrites UN

        // Store P [q][k] into UN (overwrites KT region and beyond).
#pragma unroll
        for (int i = 0; i < 8; i++) {
            *(float4*)&UN[(r0 + i) * 128 + cA] =
                make_float4(s[i][0], s[i][1], s[i][2], s[i][3]);
            *(float4*)&UN[(r0 + i) * 128 + cB] =
                make_float4(s[i][4], s[i][5], s[i][6], s[i][7]);
        }
        __syncthreads();

        // O += P V : 8q x 4d per thread, inner over 128 keys (4 at a time).
        // P reads broadcast across tx; V reads contiguous.
#pragma unroll 2
        for (int k4 = 0; k4 < 32; k4++) {
            float4 v0 = *(const float4*)&Vs[(k4 * 4 + 0) * 64 + tx * 4];
            float4 v1 = *(const float4*)&Vs[(k4 * 4 + 1) * 64 + tx * 4];
            float4 v2 = *(const float4*)&Vs[(k4 * 4 + 2) * 64 + tx * 4];
            float4 v3 = *(const float4*)&Vs[(k4 * 4 + 3) * 64 + tx * 4];
            float bv[4][4] = {{v0.x, v0.y, v0.z, v0.w},
                              {v1.x, v1.y, v1.z, v1.w},
                              {v2.x, v2.y, v2.z, v2.w},
                              {v3.x, v3.y, v3.z, v3.w}};
#pragma unroll
            for (int i = 0; i < 8; i++) {
                float4 a4 = *(const float4*)&UN[(r0 + i) * 128 + k4 * 4];
                float aa[4] = {a4.x, a4.y, a4.z, a4.w};
#pragma unroll
                for (int c = 0; c < 4; c++)
#pragma unroll
                    for (int jj = 0; jj < 4; jj++)
                        acc[i][c] = fmaf(aa[jj], bv[jj][c], acc[i][c]);
            }
        }
    }

    // Epilogue: out[b][s][h*64 + tx*4 ..]
#pragma unroll
    for (int i = 0; i < 8; i++) {
        float inv = 1.0f / lsum[i];
        float4 o = make_float4(acc[i][0] * inv, acc[i][1] * inv,
                               acc[i][2] * inv, acc[i][3] * inv);
        int srow = q0 + r0 + i;
        *(float4*)(out + ((size_t)(b * SEQ + srow)) * HID + h * HDIM + tx * 4) = o;
    }
}

extern "C" void kernel_launch(void* const* d_in, const int* in_sizes, int n_in,
                              void* d_out, int out_size) {
    const float* X    = (const float*)d_in[0];
    const int*   mask = (const int*)d_in[1];
    const float* Wq   = (const float*)d_in[2];
    const float* Bq   = (const float*)d_in[3];
    const float* Wk   = (const float*)d_in[4];
    const float* Bk   = (const float*)d_in[5];
    const float* Wv   = (const float*)d_in[6];
    const float* Bv   = (const float*)d_in[7];
    float* out = (float*)d_out;

    dim3 g1(HID / 128, (BATCH * SEQ) / 128, 3);
    qkv_kernel<<<g1, 256>>>(X, Wq, Bq, Wk, Bk, Wv, Bv);

    static const int smem_bytes = 128 * 1024;
    cudaFuncSetAttribute(attn_kernel,
                         cudaFuncAttributeMaxDynamicSharedMemorySize, smem_bytes);
    dim3 g2(SEQ / 128, BATCH * NHEAD);
    attn_kernel<<<g2, 256, smem_bytes>>>(mask, out);
}